// round 4
// baseline (speedup 1.0000x reference)
#include <cuda_runtime.h>

#define INV_SQRT2F 0.70710678118654752440f

// Full-angle contraction table: K[r][P][Qpad], P,Q in 0..8 over the basis
// (1, cos, sin) x (1, cos, sin) per qubit pair, lanes = (logit0, logit1).
// Q padded 9->10 so each row is 5 float4s (16B-aligned). Column 9 is zero.
// lin_b is folded into K[0][0][0].
__device__ float2 g_K[4][9][10];

// Per-qubit monomial -> (1, C, S) transform. i,j in {0,1} (cos/sin half-angle).
__device__ __forceinline__ float Tfac(int i, int j, int e) {
    if (i == j) return (e == 0) ? 0.5f : ((e == 1) ? (i ? -0.5f : 0.5f) : 0.0f);
    return (e == 2) ? 0.5f : 0.0f;
}

// ---------------------------------------------------------------------------
// Setup kernel (1 block x 256 threads):
// 1) M = H4*D2 * H4*D1 * H4*D0 (verified in rounds 2-3)
// 2) B_w[n][m] = sum_p sign_w(p) Re(conj(M[p][n]) M[p][m])
// 3) K[r][P][Q] = sum over ALL ordered (n,m) of C_{k,r}[n][m] * prod_w T(...)
//    -- exact basis change, no symmetry folding.
// ---------------------------------------------------------------------------
__global__ void setup_kernel(const float* __restrict__ weights,
                             const float* __restrict__ lin_w,
                             const float* __restrict__ lin_b) {
    __shared__ float2 M[16][16];     // [p][n]
    __shared__ float  B[4][16][16];
    const int t = threadIdx.x;
    const int p = t >> 4, n = t & 15;

    M[p][n] = make_float2(p == n ? 1.0f : 0.0f, 0.0f);
    __syncthreads();

    for (int l = 0; l < 3; ++l) {
        float th = 0.0f;
        #pragma unroll
        for (int i = 0; i < 4; ++i) {
            int bi = (p >> (3 - i)) & 1;                 // control wire i
            int bj = (p >> (3 - ((i + 1) & 3))) & 1;     // target wire i+1
            th += (float)bi * (float)(2 * bj - 1) * weights[4 * l + i];
        }
        th *= 0.5f;
        float sr, cr;
        sincosf(th, &sr, &cr);
        float2 v = M[p][n];
        M[p][n] = make_float2(v.x * cr - v.y * sr, v.x * sr + v.y * cr);
        __syncthreads();
        for (int w = 0; w < 4; ++w) {
            int bp = 3 - w;
            if (((p >> bp) & 1) == 0) {
                int p1 = p | (1 << bp);
                float2 v0 = M[p][n], v1 = M[p1][n];
                M[p][n]  = make_float2((v0.x + v1.x) * INV_SQRT2F,
                                       (v0.y + v1.y) * INV_SQRT2F);
                M[p1][n] = make_float2((v0.x - v1.x) * INV_SQRT2F,
                                       (v0.y - v1.y) * INV_SQRT2F);
            }
            __syncthreads();
        }
    }

    // B_w[n][m]
    {
        const int nn = t >> 4, mm = t & 15;
        float d[16];
        #pragma unroll
        for (int pp = 0; pp < 16; ++pp)
            d[pp] = M[pp][nn].x * M[pp][mm].x + M[pp][nn].y * M[pp][mm].y;
        #pragma unroll
        for (int w = 0; w < 4; ++w) {
            float acc = 0.0f;
            #pragma unroll
            for (int pp = 0; pp < 16; ++pp) {
                float sgn = ((pp >> (3 - w)) & 1) ? -1.0f : 1.0f;
                acc += sgn * d[pp];
            }
            B[w][nn][mm] = acc;
        }
    }
    __syncthreads();

    // K table: 4*9*10 = 360 entries (col 9 = zero pad).
    for (int e = t; e < 360; e += 256) {
        int r = e / 90, P = (e / 10) % 9, Q = e % 10;
        if (Q == 9) { g_K[r][P][Q] = make_float2(0.0f, 0.0f); continue; }
        int e0 = P / 3, e1 = P % 3, e2 = Q / 3, e3 = Q % 3;
        float s0 = 0.0f, s1 = 0.0f;
        for (int nn = 0; nn < 16; ++nn) {
            for (int mm = 0; mm < 16; ++mm) {
                float tp = Tfac((nn >> 3) & 1, (mm >> 3) & 1, e0)
                         * Tfac((nn >> 2) & 1, (mm >> 2) & 1, e1)
                         * Tfac((nn >> 1) & 1, (mm >> 1) & 1, e2)
                         * Tfac( nn       & 1,  mm       & 1, e3);
                if (tp == 0.0f) continue;
                float c0 = 0.0f, c1 = 0.0f;
                #pragma unroll
                for (int w = 0; w < 4; ++w) {
                    float Bw = B[w][nn][mm];
                    c0 += lin_w[4 * r + w]      * Bw;
                    c1 += lin_w[16 + 4 * r + w] * Bw;
                }
                s0 += tp * c0;
                s1 += tp * c1;
            }
        }
        if (r == 0 && P == 0 && Q == 0) { s0 += lin_b[0]; s1 += lin_b[1]; }
        g_K[r][P][Q] = make_float2(s0, s1);
    }
}

// ---------------------------------------------------------------------------
// Packed f32x2 helpers (FFMA2: 2 fp32 FMAs per instruction on sm_103a)
// ---------------------------------------------------------------------------
__device__ __forceinline__ unsigned long long pack2(float a, float b) {
    unsigned long long r;
    asm("mov.b64 %0, {%1, %2};"
        : "=l"(r) : "r"(__float_as_uint(a)), "r"(__float_as_uint(b)));
    return r;
}
__device__ __forceinline__ unsigned long long dup2(float a) {
    return pack2(a, a);
}
__device__ __forceinline__ unsigned long long fma2(unsigned long long a,
                                                   unsigned long long b,
                                                   unsigned long long c) {
    unsigned long long d;
    asm("fma.rn.f32x2 %0, %1, %2, %3;" : "=l"(d) : "l"(a), "l"(b), "l"(c));
    return d;
}

// ---------------------------------------------------------------------------
// Main kernel: one thread per sample. Per sub-batch r: 4 full-angle sincos,
// 9x9 bilinear contraction in the (1,C,S) basis with both logits packed in
// f32x2 lanes; then 2-way softmax.
// ---------------------------------------------------------------------------
__global__ void __launch_bounds__(128, 4)
main_kernel(const float* __restrict__ x,
            float2* __restrict__ out, int bsz) {
    __shared__ float2 Ksh[4][9][10];
    for (int i = threadIdx.x; i < 360; i += 128)
        (&Ksh[0][0][0])[i] = (&g_K[0][0][0])[i];
    __syncthreads();

    int b = blockIdx.x * 128 + threadIdx.x;
    if (b >= bsz) return;

    float xv[16];
    const float4* xp = reinterpret_cast<const float4*>(x + (size_t)b * 16);
    #pragma unroll
    for (int i = 0; i < 4; ++i) {
        float4 v = xp[i];
        xv[4 * i + 0] = v.x; xv[4 * i + 1] = v.y;
        xv[4 * i + 2] = v.z; xv[4 * i + 3] = v.w;
    }

    unsigned long long acc = 0ull;   // bias folded into K[0][0][0]

    #pragma unroll
    for (int r = 0; r < 4; ++r) {
        // angles of sub-batch r at flat indices base, base+1, base+4, base+5
        const int base = ((r >> 1) << 3) | ((r & 1) << 1);
        float C0, S0, C1, S1, C2, S2, C3, S3;
        __sincosf(xv[base],     &S0, &C0);
        __sincosf(xv[base + 1], &S1, &C1);
        __sincosf(xv[base + 4], &S2, &C2);
        __sincosf(xv[base + 5], &S3, &C3);

        // v23 basis (Q = 3*e2 + e3): (1,C2,S2) x (1,C3,S3)
        unsigned long long q[10];
        q[0] = dup2(1.0f);
        q[1] = dup2(C3);
        q[2] = dup2(S3);
        q[3] = dup2(C2);
        q[4] = dup2(C2 * C3);
        q[5] = dup2(C2 * S3);
        q[6] = dup2(S2);
        q[7] = dup2(S2 * C3);
        q[8] = dup2(S2 * S3);
        q[9] = 0ull;

        // v01 basis (P = 3*e0 + e1)
        float v01[9];
        v01[0] = 1.0f;
        v01[1] = C1;  v01[2] = S1;
        v01[3] = C0;  v01[4] = C0 * C1;  v01[5] = C0 * S1;
        v01[6] = S0;  v01[7] = S0 * C1;  v01[8] = S0 * S1;

        const float4* Kr = reinterpret_cast<const float4*>(&Ksh[r][0][0]);
        #pragma unroll
        for (int P = 0; P < 9; ++P) {
            unsigned long long t = 0ull;
            #pragma unroll
            for (int j = 0; j < 5; ++j) {
                float4 kv = Kr[P * 5 + j];
                t = fma2(pack2(kv.x, kv.y), q[2 * j],     t);
                t = fma2(pack2(kv.z, kv.w), q[2 * j + 1], t);
            }
            acc = fma2(dup2(v01[P]), t, acc);
        }
    }

    unsigned int lo, hi;
    asm("mov.b64 {%0, %1}, %2;" : "=r"(lo), "=r"(hi) : "l"(acc));
    float l0 = __uint_as_float(lo), l1 = __uint_as_float(hi);
    float m  = fmaxf(l0, l1);
    float e0 = __expf(l0 - m), e1 = __expf(l1 - m);
    float inv = __fdividef(1.0f, e0 + e1);
    out[b] = make_float2(e0 * inv, e1 * inv);
}

// ---------------------------------------------------------------------------
extern "C" void kernel_launch(void* const* d_in, const int* in_sizes, int n_in,
                              void* d_out, int out_size) {
    const float* x = nullptr;
    const float* weights = nullptr;
    const float* lin_w = nullptr;
    const float* lin_b = nullptr;
    for (int i = 0; i < n_in; ++i) {
        int sz = in_sizes[i];
        if (sz == 12)      weights = (const float*)d_in[i];
        else if (sz == 32) lin_w   = (const float*)d_in[i];
        else if (sz == 2)  lin_b   = (const float*)d_in[i];
        else               x       = (const float*)d_in[i];
    }
    int bsz = out_size / 2;
    setup_kernel<<<1, 256>>>(weights, lin_w, lin_b);
    int threads = 128;
    int blocks  = (bsz + threads - 1) / threads;
    main_kernel<<<blocks, threads>>>(x, (float2*)d_out, bsz);
}

// round 5
// speedup vs baseline: 4.5042x; 4.5042x over previous
#include <cuda_runtime.h>

#define INV_SQRT2F 0.70710678118654752440f

// g_C[r][n][m] = (sum_w lin_w[0][4r+w] B_w[n][m], sum_w lin_w[1][4r+w] B_w[n][m])
__device__ float2 g_C[4][16][16];
// Full-angle contraction table K[r][P][Qpad], P,Q in 0..8 over (1,C,S)x(1,C,S),
// lanes = (logit0, logit1). Q padded to 10 (col 9 zero) -> 5 float4 per row.
// lin_b folded into K[0][0][0].
__device__ float2 g_K[4][9][10];

// Per-qubit half-angle-monomial -> (1, C, S) transform coefficient.
__device__ __forceinline__ float Tfac(int i, int j, int e) {
    if (i == j) return (e == 0) ? 0.5f : ((e == 1) ? (i ? -0.5f : 0.5f) : 0.0f);
    return (e == 2) ? 0.5f : 0.0f;
}

// ---------------------------------------------------------------------------
// setup_a (1 block x 256): M = H4*D2*H4*D1*H4*D0; B_w; fold lin_w -> g_C.
// ---------------------------------------------------------------------------
__global__ void setup_a(const float* __restrict__ weights,
                        const float* __restrict__ lin_w) {
    __shared__ float2 M[16][16];
    __shared__ float  B[4][16][16];
    const int t = threadIdx.x;
    const int p = t >> 4, n = t & 15;

    M[p][n] = make_float2(p == n ? 1.0f : 0.0f, 0.0f);
    __syncthreads();

    for (int l = 0; l < 3; ++l) {
        float th = 0.0f;
        #pragma unroll
        for (int i = 0; i < 4; ++i) {
            int bi = (p >> (3 - i)) & 1;                 // control wire i
            int bj = (p >> (3 - ((i + 1) & 3))) & 1;     // target wire i+1
            th += (float)bi * (float)(2 * bj - 1) * weights[4 * l + i];
        }
        th *= 0.5f;
        float sr, cr;
        sincosf(th, &sr, &cr);
        float2 v = M[p][n];
        M[p][n] = make_float2(v.x * cr - v.y * sr, v.x * sr + v.y * cr);
        __syncthreads();
        for (int w = 0; w < 4; ++w) {
            int bp = 3 - w;
            if (((p >> bp) & 1) == 0) {
                int p1 = p | (1 << bp);
                float2 v0 = M[p][n], v1 = M[p1][n];
                M[p][n]  = make_float2((v0.x + v1.x) * INV_SQRT2F,
                                       (v0.y + v1.y) * INV_SQRT2F);
                M[p1][n] = make_float2((v0.x - v1.x) * INV_SQRT2F,
                                       (v0.y - v1.y) * INV_SQRT2F);
            }
            __syncthreads();
        }
    }

    // B_w[n][m] = sum_p sign_w(p) Re(conj(M[p][n]) M[p][m])
    {
        const int nn = t >> 4, mm = t & 15;
        float d[16];
        #pragma unroll
        for (int pp = 0; pp < 16; ++pp)
            d[pp] = M[pp][nn].x * M[pp][mm].x + M[pp][nn].y * M[pp][mm].y;
        #pragma unroll
        for (int w = 0; w < 4; ++w) {
            float acc = 0.0f;
            #pragma unroll
            for (int pp = 0; pp < 16; ++pp) {
                float sgn = ((pp >> (3 - w)) & 1) ? -1.0f : 1.0f;
                acc += sgn * d[pp];
            }
            B[w][nn][mm] = acc;
        }
        __syncthreads();
        #pragma unroll
        for (int r = 0; r < 4; ++r) {
            float c0 = 0.0f, c1 = 0.0f;
            #pragma unroll
            for (int w = 0; w < 4; ++w) {
                float Bw = B[w][nn][mm];
                c0 += lin_w[4 * r + w]      * Bw;
                c1 += lin_w[16 + 4 * r + w] * Bw;
            }
            g_C[r][nn][mm] = make_float2(c0, c1);
        }
    }
}

// ---------------------------------------------------------------------------
// setup_b (45 blocks x 256 = 360 warps): one warp per K entry; lanes split the
// 256 (n,m) pairs; shfl reduce. Exact basis change, no symmetry reasoning.
// ---------------------------------------------------------------------------
__global__ void setup_b(const float* __restrict__ lin_b) {
    int gw = (blockIdx.x * blockDim.x + threadIdx.x) >> 5;   // 0..359
    int lane = threadIdx.x & 31;
    if (gw >= 360) return;
    int r = gw / 90, rem = gw % 90, P = rem / 10, Q = rem % 10;
    if (Q == 9) {                                   // zero pad column
        if (lane == 0) g_K[r][P][9] = make_float2(0.0f, 0.0f);
        return;
    }
    int e0 = P / 3, e1 = P % 3, e2 = Q / 3, e3 = Q % 3;
    float s0 = 0.0f, s1 = 0.0f;
    #pragma unroll
    for (int i = 0; i < 8; ++i) {
        int pair = i * 32 + lane;
        int nn = pair >> 4, mm = pair & 15;
        float tp = Tfac((nn >> 3) & 1, (mm >> 3) & 1, e0)
                 * Tfac((nn >> 2) & 1, (mm >> 2) & 1, e1)
                 * Tfac((nn >> 1) & 1, (mm >> 1) & 1, e2)
                 * Tfac( nn       & 1,  mm       & 1, e3);
        if (tp != 0.0f) {
            float2 c = g_C[r][nn][mm];
            s0 += tp * c.x;
            s1 += tp * c.y;
        }
    }
    #pragma unroll
    for (int off = 16; off > 0; off >>= 1) {
        s0 += __shfl_down_sync(0xffffffffu, s0, off);
        s1 += __shfl_down_sync(0xffffffffu, s1, off);
    }
    if (lane == 0) {
        if (r == 0 && P == 0 && Q == 0) { s0 += lin_b[0]; s1 += lin_b[1]; }
        g_K[r][P][Q] = make_float2(s0, s1);
    }
}

// ---------------------------------------------------------------------------
// Packed f32x2 helpers
// ---------------------------------------------------------------------------
__device__ __forceinline__ unsigned long long pack2(float a, float b) {
    unsigned long long r;
    asm("mov.b64 %0, {%1, %2};"
        : "=l"(r) : "r"(__float_as_uint(a)), "r"(__float_as_uint(b)));
    return r;
}
__device__ __forceinline__ unsigned long long dup2(float a) { return pack2(a, a); }
__device__ __forceinline__ unsigned long long fma2(unsigned long long a,
                                                   unsigned long long b,
                                                   unsigned long long c) {
    unsigned long long d;
    asm("fma.rn.f32x2 %0, %1, %2, %3;" : "=l"(d) : "l"(a), "l"(b), "l"(c));
    return d;
}

// ---------------------------------------------------------------------------
// Main kernel: TWO samples per thread (shares every K-row LDS between them,
// doubles FFMA ILP). Per sample/sub-batch: 4 sincos, 9x9 f32x2 contraction.
// ---------------------------------------------------------------------------
__global__ void __launch_bounds__(256, 2)
main_kernel(const float* __restrict__ x,
            float2* __restrict__ out, int bsz) {
    __shared__ float2 Ksh[4][9][10];
    for (int i = threadIdx.x; i < 360; i += 256)
        (&Ksh[0][0][0])[i] = (&g_K[0][0][0])[i];
    __syncthreads();

    const int half = (bsz + 1) >> 1;
    const int idx = blockIdx.x * 256 + threadIdx.x;
    if (idx >= half) return;
    const int sA = idx;
    const int sB = idx + half;
    const bool hasB = (sB < bsz);

    float4 xA[4], xB[4];
    {
        const float4* pa = reinterpret_cast<const float4*>(x + (size_t)sA * 16);
        const float4* pb = reinterpret_cast<const float4*>(x + (size_t)(hasB ? sB : sA) * 16);
        #pragma unroll
        for (int i = 0; i < 4; ++i) { xA[i] = pa[i]; xB[i] = pb[i]; }
    }

    unsigned long long accA = 0ull, accB = 0ull;  // bias folded into K

    #pragma unroll
    for (int r = 0; r < 4; ++r) {
        const int i0 = (r >> 1) << 1;
        const bool hi = (r & 1);

        float aA0 = hi ? xA[i0].z : xA[i0].x,   aA1 = hi ? xA[i0].w : xA[i0].y;
        float aA2 = hi ? xA[i0+1].z : xA[i0+1].x, aA3 = hi ? xA[i0+1].w : xA[i0+1].y;
        float aB0 = hi ? xB[i0].z : xB[i0].x,   aB1 = hi ? xB[i0].w : xB[i0].y;
        float aB2 = hi ? xB[i0+1].z : xB[i0+1].x, aB3 = hi ? xB[i0+1].w : xB[i0+1].y;

        float CA0,SA0,CA1,SA1,CA2,SA2,CA3,SA3;
        float CB0,SB0,CB1,SB1,CB2,SB2,CB3,SB3;
        __sincosf(aA0, &SA0, &CA0); __sincosf(aA1, &SA1, &CA1);
        __sincosf(aA2, &SA2, &CA2); __sincosf(aA3, &SA3, &CA3);
        __sincosf(aB0, &SB0, &CB0); __sincosf(aB1, &SB1, &CB1);
        __sincosf(aB2, &SB2, &CB2); __sincosf(aB3, &SB3, &CB3);

        unsigned long long qA[9], qB[9];
        qA[0]=dup2(1.0f);    qA[1]=dup2(CA3);      qA[2]=dup2(SA3);
        qA[3]=dup2(CA2);     qA[4]=dup2(CA2*CA3);  qA[5]=dup2(CA2*SA3);
        qA[6]=dup2(SA2);     qA[7]=dup2(SA2*CA3);  qA[8]=dup2(SA2*SA3);
        qB[0]=dup2(1.0f);    qB[1]=dup2(CB3);      qB[2]=dup2(SB3);
        qB[3]=dup2(CB2);     qB[4]=dup2(CB2*CB3);  qB[5]=dup2(CB2*SB3);
        qB[6]=dup2(SB2);     qB[7]=dup2(SB2*CB3);  qB[8]=dup2(SB2*SB3);

        float vA[9], vB[9];
        vA[0]=1.0f; vA[1]=CA1;     vA[2]=SA1;
        vA[3]=CA0;  vA[4]=CA0*CA1; vA[5]=CA0*SA1;
        vA[6]=SA0;  vA[7]=SA0*CA1; vA[8]=SA0*SA1;
        vB[0]=1.0f; vB[1]=CB1;     vB[2]=SB1;
        vB[3]=CB0;  vB[4]=CB0*CB1; vB[5]=CB0*SB1;
        vB[6]=SB0;  vB[7]=SB0*CB1; vB[8]=SB0*SB1;

        const float4* Kr = reinterpret_cast<const float4*>(&Ksh[r][0][0]);
        #pragma unroll
        for (int P = 0; P < 9; ++P) {
            unsigned long long tA = 0ull, tB = 0ull;
            #pragma unroll
            for (int j = 0; j < 4; ++j) {
                float4 kv = Kr[P * 5 + j];
                unsigned long long k01 = pack2(kv.x, kv.y);
                unsigned long long k23 = pack2(kv.z, kv.w);
                tA = fma2(k01, qA[2*j], tA); tA = fma2(k23, qA[2*j+1], tA);
                tB = fma2(k01, qB[2*j], tB); tB = fma2(k23, qB[2*j+1], tB);
            }
            float4 kv = Kr[P * 5 + 4];                  // (K8, pad)
            unsigned long long k8 = pack2(kv.x, kv.y);
            tA = fma2(k8, qA[8], tA);
            tB = fma2(k8, qB[8], tB);
            accA = fma2(dup2(vA[P]), tA, accA);
            accB = fma2(dup2(vB[P]), tB, accB);
        }
    }

    {
        unsigned int lo, hi2;
        asm("mov.b64 {%0, %1}, %2;" : "=r"(lo), "=r"(hi2) : "l"(accA));
        float l0 = __uint_as_float(lo), l1 = __uint_as_float(hi2);
        float m  = fmaxf(l0, l1);
        float e0 = __expf(l0 - m), e1 = __expf(l1 - m);
        float inv = __fdividef(1.0f, e0 + e1);
        out[sA] = make_float2(e0 * inv, e1 * inv);
    }
    if (hasB) {
        unsigned int lo, hi2;
        asm("mov.b64 {%0, %1}, %2;" : "=r"(lo), "=r"(hi2) : "l"(accB));
        float l0 = __uint_as_float(lo), l1 = __uint_as_float(hi2);
        float m  = fmaxf(l0, l1);
        float e0 = __expf(l0 - m), e1 = __expf(l1 - m);
        float inv = __fdividef(1.0f, e0 + e1);
        out[sB] = make_float2(e0 * inv, e1 * inv);
    }
}

// ---------------------------------------------------------------------------
extern "C" void kernel_launch(void* const* d_in, const int* in_sizes, int n_in,
                              void* d_out, int out_size) {
    const float* x = nullptr;
    const float* weights = nullptr;
    const float* lin_w = nullptr;
    const float* lin_b = nullptr;
    for (int i = 0; i < n_in; ++i) {
        int sz = in_sizes[i];
        if (sz == 12)      weights = (const float*)d_in[i];
        else if (sz == 32) lin_w   = (const float*)d_in[i];
        else if (sz == 2)  lin_b   = (const float*)d_in[i];
        else               x       = (const float*)d_in[i];
    }
    int bsz = out_size / 2;
    setup_a<<<1, 256>>>(weights, lin_w);
    setup_b<<<45, 256>>>(lin_b);
    int half = (bsz + 1) >> 1;
    int blocks = (half + 255) / 256;
    main_kernel<<<blocks, 256>>>(x, (float2*)d_out, bsz);
}

// round 6
// speedup vs baseline: 5.4780x; 1.2162x over previous
#include <cuda_runtime.h>

#define INV_SQRT2F 0.70710678118654752440f

// Full-angle contraction table K[r][P][Qpad], P,Q in 0..8 over (1,C,S)x(1,C,S)
// per qubit pair, lanes = (logit0, logit1). Q padded to 10 (col 9 zero) so each
// row is 5 float4. lin_b folded into K[0][0][0].
__device__ float2 g_K[4][9][10];

// ---------------------------------------------------------------------------
// Single setup kernel (1 block x 512):
//  Phase 1 (warp 0): register-resident columns of M = H4*D2*H4*D1*H4*D0.
//  Phase 2 (threads 0..255): B_w[n][m], then C_r[n][m] (lin_w folded).
//  Phase 3 (threads 0..359): K[r][P][Q] = sum of 16 signed C entries
//    (the per-qubit half-angle->full-angle transform has exactly 2 nonzero
//     (i,j) combos per basis index e: e=0:(00,+)(11,+); e=1:(00,+)(11,-);
//     e=2:(01,+)(10,+); coefficient 0.5 each -> product 0.0625*sign).
// ---------------------------------------------------------------------------
__global__ void setup_all(const float* __restrict__ weights,
                          const float* __restrict__ lin_w,
                          const float* __restrict__ lin_b) {
    __shared__ float2 Msh[16][16];      // [p][n]
    __shared__ float  Bsh[4][16][16];
    __shared__ float2 Csh[4][16][16];
    const int t = threadIdx.x;

    if (t < 32) {
        const int n = t & 15;
        float2 m[16];
        #pragma unroll
        for (int p = 0; p < 16; ++p)
            m[p] = make_float2(p == n ? 1.0f : 0.0f, 0.0f);

        for (int l = 0; l < 3; ++l) {
            // lane p computes the CRZ-ring phase of basis state p
            float th = 0.0f;
            {
                const int p = t & 15;
                #pragma unroll
                for (int i = 0; i < 4; ++i) {
                    int bi = (p >> (3 - i)) & 1;               // control wire i
                    int bj = (p >> (3 - ((i + 1) & 3))) & 1;   // target wire i+1
                    th += (float)bi * (float)(2 * bj - 1) * weights[4 * l + i];
                }
                th *= 0.5f;
            }
            float sr, cr;
            sincosf(th, &sr, &cr);
            #pragma unroll
            for (int p = 0; p < 16; ++p) {
                float crp = __shfl_sync(0xffffffffu, cr, p);
                float srp = __shfl_sync(0xffffffffu, sr, p);
                float2 v = m[p];
                m[p] = make_float2(v.x * crp - v.y * srp,
                                   v.x * srp + v.y * crp);
            }
            // H on every wire: in-register butterflies
            #pragma unroll
            for (int w = 0; w < 4; ++w) {
                const int bit = 8 >> w;
                #pragma unroll
                for (int p = 0; p < 16; ++p) {
                    if ((p & bit) == 0) {
                        int p1 = p | bit;
                        float2 a = m[p], b = m[p1];
                        m[p]  = make_float2((a.x + b.x) * INV_SQRT2F,
                                            (a.y + b.y) * INV_SQRT2F);
                        m[p1] = make_float2((a.x - b.x) * INV_SQRT2F,
                                            (a.y - b.y) * INV_SQRT2F);
                    }
                }
            }
        }
        if (t < 16) {
            #pragma unroll
            for (int p = 0; p < 16; ++p) Msh[p][n] = m[p];
        }
    }
    __syncthreads();

    if (t < 256) {
        const int nn = t >> 4, mm = t & 15;
        float d[16];
        #pragma unroll
        for (int pp = 0; pp < 16; ++pp)
            d[pp] = Msh[pp][nn].x * Msh[pp][mm].x +
                    Msh[pp][nn].y * Msh[pp][mm].y;
        #pragma unroll
        for (int w = 0; w < 4; ++w) {
            float acc = 0.0f;
            #pragma unroll
            for (int pp = 0; pp < 16; ++pp)
                acc += (((pp >> (3 - w)) & 1) ? -1.0f : 1.0f) * d[pp];
            Bsh[w][nn][mm] = acc;
        }
        #pragma unroll
        for (int r = 0; r < 4; ++r) {
            float c0 = 0.0f, c1 = 0.0f;
            #pragma unroll
            for (int w = 0; w < 4; ++w) {
                float Bw = Bsh[w][nn][mm];
                c0 += lin_w[4 * r + w]      * Bw;
                c1 += lin_w[16 + 4 * r + w] * Bw;
            }
            Csh[r][nn][mm] = make_float2(c0, c1);
        }
    }
    __syncthreads();

    if (t < 360) {
        const int r = t / 90, rem = t % 90, P = rem / 10, Q = rem % 10;
        if (Q == 9) {
            g_K[r][P][9] = make_float2(0.0f, 0.0f);
        } else {
            const int e0 = P / 3, e1 = P % 3, e2 = Q / 3, e3 = Q % 3;
            const int ev[4] = {e0, e1, e2, e3};
            float s0 = 0.0f, s1 = 0.0f;
            #pragma unroll
            for (int c = 0; c < 16; ++c) {
                int nn = 0, mm = 0;
                float sign = 0.0625f;
                #pragma unroll
                for (int w = 0; w < 4; ++w) {
                    int b = (c >> w) & 1;
                    int i, j;
                    if (ev[w] == 2) { i = b; j = 1 - b; }
                    else { i = b; j = b; if (ev[w] == 1 && b == 1) sign = -sign; }
                    nn |= i << (3 - w);
                    mm |= j << (3 - w);
                }
                float2 cv = Csh[r][nn][mm];
                s0 += sign * cv.x;
                s1 += sign * cv.y;
            }
            if (t == 0) { s0 += lin_b[0]; s1 += lin_b[1]; }
            g_K[r][P][Q] = make_float2(s0, s1);
        }
    }
}

// ---------------------------------------------------------------------------
// Packed f32x2 helpers
// ---------------------------------------------------------------------------
__device__ __forceinline__ unsigned long long pack2(float a, float b) {
    unsigned long long r;
    asm("mov.b64 %0, {%1, %2};"
        : "=l"(r) : "r"(__float_as_uint(a)), "r"(__float_as_uint(b)));
    return r;
}
__device__ __forceinline__ unsigned long long dup2(float a) { return pack2(a, a); }
__device__ __forceinline__ unsigned long long fma2(unsigned long long a,
                                                   unsigned long long b,
                                                   unsigned long long c) {
    unsigned long long d;
    asm("fma.rn.f32x2 %0, %1, %2, %3;" : "=l"(d) : "l"(a), "l"(b), "l"(c));
    return d;
}

// ---------------------------------------------------------------------------
// Main kernel: two samples per thread; per sample & sub-batch r: 4 sincos,
// 9x9 f32x2 contraction (t initialized from K[P][0] since q[0] == 1).
// ---------------------------------------------------------------------------
__global__ void __launch_bounds__(256, 2)
main_kernel(const float* __restrict__ x,
            float2* __restrict__ out, int bsz) {
    __shared__ float2 Ksh[4][9][10];
    for (int i = threadIdx.x; i < 360; i += 256)
        (&Ksh[0][0][0])[i] = (&g_K[0][0][0])[i];
    __syncthreads();

    const int half = (bsz + 1) >> 1;
    const int idx = blockIdx.x * 256 + threadIdx.x;
    if (idx >= half) return;
    const int sA = idx;
    const int sB = idx + half;
    const bool hasB = (sB < bsz);

    float4 xA[4], xB[4];
    {
        const float4* pa = reinterpret_cast<const float4*>(x + (size_t)sA * 16);
        const float4* pb = reinterpret_cast<const float4*>(x + (size_t)(hasB ? sB : sA) * 16);
        #pragma unroll
        for (int i = 0; i < 4; ++i) { xA[i] = pa[i]; xB[i] = pb[i]; }
    }

    unsigned long long accA = 0ull, accB = 0ull;  // bias folded into K

    #pragma unroll
    for (int r = 0; r < 4; ++r) {
        const int i0 = (r >> 1) << 1;
        const bool hi = (r & 1);

        float aA0 = hi ? xA[i0].z : xA[i0].x,     aA1 = hi ? xA[i0].w : xA[i0].y;
        float aA2 = hi ? xA[i0+1].z : xA[i0+1].x, aA3 = hi ? xA[i0+1].w : xA[i0+1].y;
        float aB0 = hi ? xB[i0].z : xB[i0].x,     aB1 = hi ? xB[i0].w : xB[i0].y;
        float aB2 = hi ? xB[i0+1].z : xB[i0+1].x, aB3 = hi ? xB[i0+1].w : xB[i0+1].y;

        float CA0,SA0,CA1,SA1,CA2,SA2,CA3,SA3;
        float CB0,SB0,CB1,SB1,CB2,SB2,CB3,SB3;
        __sincosf(aA0, &SA0, &CA0); __sincosf(aA1, &SA1, &CA1);
        __sincosf(aA2, &SA2, &CA2); __sincosf(aA3, &SA3, &CA3);
        __sincosf(aB0, &SB0, &CB0); __sincosf(aB1, &SB1, &CB1);
        __sincosf(aB2, &SB2, &CB2); __sincosf(aB3, &SB3, &CB3);

        unsigned long long qA[9], qB[9];
        qA[1]=dup2(CA3);      qA[2]=dup2(SA3);
        qA[3]=dup2(CA2);      qA[4]=dup2(CA2*CA3);  qA[5]=dup2(CA2*SA3);
        qA[6]=dup2(SA2);      qA[7]=dup2(SA2*CA3);  qA[8]=dup2(SA2*SA3);
        qB[1]=dup2(CB3);      qB[2]=dup2(SB3);
        qB[3]=dup2(CB2);      qB[4]=dup2(CB2*CB3);  qB[5]=dup2(CB2*SB3);
        qB[6]=dup2(SB2);      qB[7]=dup2(SB2*CB3);  qB[8]=dup2(SB2*SB3);

        float vA[9], vB[9];
        vA[0]=1.0f; vA[1]=CA1;     vA[2]=SA1;
        vA[3]=CA0;  vA[4]=CA0*CA1; vA[5]=CA0*SA1;
        vA[6]=SA0;  vA[7]=SA0*CA1; vA[8]=SA0*SA1;
        vB[0]=1.0f; vB[1]=CB1;     vB[2]=SB1;
        vB[3]=CB0;  vB[4]=CB0*CB1; vB[5]=CB0*SB1;
        vB[6]=SB0;  vB[7]=SB0*CB1; vB[8]=SB0*SB1;

        const float4* Kr = reinterpret_cast<const float4*>(&Ksh[r][0][0]);
        #pragma unroll
        for (int P = 0; P < 9; ++P) {
            float4 k0 = Kr[P * 5 + 0];            // (K[P][0], K[P][1])
            unsigned long long tA = pack2(k0.x, k0.y);   // q[0] == 1
            unsigned long long tB = tA;
            unsigned long long k1 = pack2(k0.z, k0.w);
            tA = fma2(k1, qA[1], tA); tB = fma2(k1, qB[1], tB);
            #pragma unroll
            for (int j = 1; j < 4; ++j) {
                float4 kv = Kr[P * 5 + j];
                unsigned long long ka = pack2(kv.x, kv.y);
                unsigned long long kb = pack2(kv.z, kv.w);
                tA = fma2(ka, qA[2*j],   tA);
                tA = fma2(kb, qA[2*j+1], tA);
                tB = fma2(ka, qB[2*j],   tB);
                tB = fma2(kb, qB[2*j+1], tB);
            }
            float4 kv4 = Kr[P * 5 + 4];           // (K[P][8], pad)
            unsigned long long k8 = pack2(kv4.x, kv4.y);
            tA = fma2(k8, qA[8], tA);
            tB = fma2(k8, qB[8], tB);
            accA = fma2(dup2(vA[P]), tA, accA);
            accB = fma2(dup2(vB[P]), tB, accB);
        }
    }

    {
        unsigned int lo, hi2;
        asm("mov.b64 {%0, %1}, %2;" : "=r"(lo), "=r"(hi2) : "l"(accA));
        float l0 = __uint_as_float(lo), l1 = __uint_as_float(hi2);
        float m  = fmaxf(l0, l1);
        float e0 = __expf(l0 - m), e1 = __expf(l1 - m);
        float inv = __fdividef(1.0f, e0 + e1);
        out[sA] = make_float2(e0 * inv, e1 * inv);
    }
    if (hasB) {
        unsigned int lo, hi2;
        asm("mov.b64 {%0, %1}, %2;" : "=r"(lo), "=r"(hi2) : "l"(accB));
        float l0 = __uint_as_float(lo), l1 = __uint_as_float(hi2);
        float m  = fmaxf(l0, l1);
        float e0 = __expf(l0 - m), e1 = __expf(l1 - m);
        float inv = __fdividef(1.0f, e0 + e1);
        out[sB] = make_float2(e0 * inv, e1 * inv);
    }
}

// ---------------------------------------------------------------------------
extern "C" void kernel_launch(void* const* d_in, const int* in_sizes, int n_in,
                              void* d_out, int out_size) {
    const float* x = nullptr;
    const float* weights = nullptr;
    const float* lin_w = nullptr;
    const float* lin_b = nullptr;
    for (int i = 0; i < n_in; ++i) {
        int sz = in_sizes[i];
        if (sz == 12)      weights = (const float*)d_in[i];
        else if (sz == 32) lin_w   = (const float*)d_in[i];
        else if (sz == 2)  lin_b   = (const float*)d_in[i];
        else               x       = (const float*)d_in[i];
    }
    int bsz = out_size / 2;
    setup_all<<<1, 512>>>(weights, lin_w, lin_b);
    int half = (bsz + 1) >> 1;
    int blocks = (half + 255) / 256;
    main_kernel<<<blocks, 256>>>(x, (float2*)d_out, bsz);
}